// round 1
// baseline (speedup 1.0000x reference)
#include <cuda_runtime.h>
#include <stdint.h>

// Problem constants
#define NB   32
#define HH   56
#define WW   56
#define CI   256
#define CO   256
#define HP   58     // padded
#define WP   58
#define CP4  64     // CI/4 int32 packs per pixel
#define K9   9
#define NW_ELEM (3*3*CI*CO)          // 589824 weight elements
#define TW   28                       // output pixels per block (56 = 2*28)

// ---------------- scratch (device globals; no allocation allowed) ----------
__device__ int   g_act[NB * HP * WP * CP4];     // padded quantized acts, 4x s8 per int
__device__ int   g_wt[K9 * CP4 * CO];           // sign-packed weights [k9][cp][co]
__device__ float g_partial[576];
__device__ float g_E;

// ---------------- 1a. partial sums of |W| ----------------------------------
__global__ void __launch_bounds__(256) reduce_absw_1(const float* __restrict__ W) {
    __shared__ float sh[256];
    int b = blockIdx.x;            // 576 blocks * 1024 elems = 589824 exactly
    int t = threadIdx.x;
    const float* p = W + b * 1024;
    float s = fabsf(p[t]) + fabsf(p[t + 256]) + fabsf(p[t + 512]) + fabsf(p[t + 768]);
    sh[t] = s;
    __syncthreads();
    for (int o = 128; o > 0; o >>= 1) {
        if (t < o) sh[t] += sh[t + o];
        __syncthreads();
    }
    if (t == 0) g_partial[b] = sh[0];
}

// ---------------- 1b. final mean --------------------------------------------
__global__ void __launch_bounds__(256) reduce_absw_2() {
    __shared__ float sh[256];
    int t = threadIdx.x;
    float s = g_partial[t] + g_partial[t + 256];
    if (t < 576 - 512) s += g_partial[t + 512];
    sh[t] = s;
    __syncthreads();
    for (int o = 128; o > 0; o >>= 1) {
        if (t < o) sh[t] += sh[t + o];
        __syncthreads();
    }
    if (t == 0) g_E = sh[0] / (float)NW_ELEM;
}

// ---------------- 2. quantize activations into padded s8 buffer ------------
// a = round_to_nearest_even( min(1,|x|) * 7 )  in {0..7}; border = 0
__global__ void __launch_bounds__(256) quantize_x(const float* __restrict__ x) {
    int idx = blockIdx.x * 256 + threadIdx.x;          // over NB*HP*WP*CP4
    if (idx >= NB * HP * WP * CP4) return;
    int c4 = idx & (CP4 - 1);
    int t  = idx >> 6;                                  // /CP4
    int wp = t % WP;
    t /= WP;
    int hp = t % HP;
    int n  = t / HP;
    int pack = 0;
    if (hp >= 1 && hp <= HH && wp >= 1 && wp <= WW) {
        const float4 v = *reinterpret_cast<const float4*>(
            x + (((size_t)(n * HH + (hp - 1)) * WW + (wp - 1)) * CI + c4 * 4));
        int a0 = __float2int_rn(fminf(1.0f, fabsf(v.x)) * 7.0f);
        int a1 = __float2int_rn(fminf(1.0f, fabsf(v.y)) * 7.0f);
        int a2 = __float2int_rn(fminf(1.0f, fabsf(v.z)) * 7.0f);
        int a3 = __float2int_rn(fminf(1.0f, fabsf(v.w)) * 7.0f);
        pack = (a0 & 0xff) | ((a1 & 0xff) << 8) | ((a2 & 0xff) << 16) | ((a3 & 0xff) << 24);
    }
    g_act[idx] = pack;
}

// ---------------- 3. weight sign transpose: [k9][cp][co] -------------------
// W is HWIO: W[((k9)*CI + ci)*CO + co]; sign matches jnp.sign (0 -> 0)
__global__ void __launch_bounds__(256) wtrans(const float* __restrict__ W) {
    int idx = blockIdx.x * 256 + threadIdx.x;          // 9*64*256 = 147456 = 576*256
    int co = idx & (CO - 1);
    int cp = (idx >> 8) & (CP4 - 1);
    int k9 = idx >> 14;
    int pack = 0;
#pragma unroll
    for (int j = 0; j < 4; j++) {
        float f = W[((size_t)(k9 * CI + cp * 4 + j)) * CO + co];
        int s = (f > 0.0f) - (f < 0.0f);
        pack |= (s & 0xff) << (8 * j);
    }
    g_wt[(k9 * CP4 + cp) * CO + co] = pack;
}

// ---------------- 4. int8 direct conv + fused epilogue ---------------------
// grid: (2, 56, 32); block: 256 threads (thread = cout)
__global__ void __launch_bounds__(256) conv_dp4a(const float* __restrict__ bias,
                                                 float* __restrict__ out) {
    const int co = threadIdx.x;
    const int w0 = blockIdx.x * TW;     // 0 or 28
    const int h  = blockIdx.y;
    const int n  = blockIdx.z;

    // SMEM tile: 3 padded rows (h..h+2), 30 pixels (w0..w0+29), 64 int packs
    __shared__ int s_act[3 * 30 * CP4];  // 23040 B
    {
        int4* s4 = reinterpret_cast<int4*>(s_act);
        const int4* g4 = reinterpret_cast<const int4*>(g_act);
        for (int i = threadIdx.x; i < 3 * 30 * 16; i += 256) {   // 1440 int4
            int r = i / 480;
            int rem = i - r * 480;
            s4[r * 480 + rem] = g4[((size_t)((n * HP + h + r) * WP) + w0) * 16 + rem];
        }
    }
    __syncthreads();

    int acc[TW];
#pragma unroll
    for (int p = 0; p < TW; p++) acc[p] = 0;

    for (int k9 = 0; k9 < K9; k9++) {
        const int kh = k9 / 3;
        const int kw = k9 - kh * 3;
        const int* __restrict__ srow = s_act + (kh * 30 + kw) * CP4;
        const int* __restrict__ wrow = g_wt + k9 * CP4 * CO + co;
#pragma unroll 2
        for (int cp = 0; cp < CP4; cp++) {
            const int w = wrow[cp * CO];
            const int* a = srow + cp;
#pragma unroll
            for (int p = 0; p < TW; p++) {
                acc[p] = __dp4a(a[p * CP4], w, acc[p]);
            }
        }
    }

    const float scale = g_E * (1.0f / 7.0f);
    const float bv = bias[co];
    size_t obase = ((size_t)(n * HH + h) * WW + w0) * CO + co;
#pragma unroll
    for (int p = 0; p < TW; p++) {
        out[obase + (size_t)p * CO] = (float)acc[p] * scale + bv;
    }
}

// ---------------- launch ----------------------------------------------------
extern "C" void kernel_launch(void* const* d_in, const int* in_sizes, int n_in,
                              void* d_out, int out_size) {
    const float* x = (const float*)d_in[0];
    const float* W = (const float*)d_in[1];
    const float* b = (const float*)d_in[2];
    float* out = (float*)d_out;

    reduce_absw_1<<<576, 256>>>(W);
    reduce_absw_2<<<1, 256>>>();

    int qtot = NB * HP * WP * CP4;                 // 6,885,376
    quantize_x<<<(qtot + 255) / 256, 256>>>(x);

    wtrans<<<576, 256>>>(W);

    dim3 grid(WW / TW, HH, NB);                    // (2, 56, 32)
    conv_dp4a<<<grid, 256>>>(b, out);
}

// round 3
// speedup vs baseline: 1.0587x; 1.0587x over previous
#include <cuda_runtime.h>
#include <stdint.h>

// ---------------- problem constants ----------------------------------------
#define NB   32
#define HH   56
#define WW   56
#define CI   256
#define CO   256
#define HP   58
#define WP   58
#define K9   9
#define NPIX (NB*HH*WW)          // 100352
#define NTILE (NPIX/128)         // 784
#define NKS   72                 // K = 2304 in steps of 32
#define NW_ELEM (K9*CI*CO)       // 589824

#define STAGES      3
#define A_BYTES     6144         // 128 rows x 48B (32B data + 16B pad)
#define STAGE_BYTES 12288        // A + B
#define ROWPAD      48

// ---------------- device scratch --------------------------------------------
__device__ int   g_act[NB * HP * WP * 64];   // padded s8 acts (4/int), 27.5 MB
__device__ int   g_wt[CO * 576];             // s8 signs, [co][k9][ci] col-major packs
__device__ float g_partial[576];
__device__ float g_E;

// ---------------- PTX helpers ------------------------------------------------
__device__ __forceinline__ uint32_t smem_u32(const void* p) {
    uint32_t a;
    asm("{ .reg .u64 t; cvta.to.shared.u64 t, %1; cvt.u32.u64 %0, t; }" : "=r"(a) : "l"(p));
    return a;
}
#define CP_ASYNC16(dst, src) \
    asm volatile("cp.async.cg.shared.global [%0], [%1], 16;" \
        :: "r"(dst), "l"(__cvta_generic_to_global(src)))
#define CP_COMMIT() asm volatile("cp.async.commit_group;" ::: "memory")
#define CP_WAIT(n)  asm volatile("cp.async.wait_group %0;" :: "n"(n) : "memory")

__device__ __forceinline__ void imma16832(int* d, uint32_t a0, uint32_t a1,
                                          uint32_t a2, uint32_t a3,
                                          uint32_t b0, uint32_t b1) {
    asm volatile(
        "mma.sync.aligned.m16n8k32.row.col.s32.s8.s8.s32 "
        "{%0,%1,%2,%3}, {%4,%5,%6,%7}, {%8,%9}, {%0,%1,%2,%3};"
        : "+r"(d[0]), "+r"(d[1]), "+r"(d[2]), "+r"(d[3])
        : "r"(a0), "r"(a1), "r"(a2), "r"(a3), "r"(b0), "r"(b1));
}

// ---------------- 1. E = mean|W| ---------------------------------------------
__global__ void __launch_bounds__(256) reduce_absw_1(const float* __restrict__ W) {
    __shared__ float sh[256];
    int b = blockIdx.x, t = threadIdx.x;
    const float* p = W + b * 1024;
    sh[t] = fabsf(p[t]) + fabsf(p[t + 256]) + fabsf(p[t + 512]) + fabsf(p[t + 768]);
    __syncthreads();
    for (int o = 128; o > 0; o >>= 1) { if (t < o) sh[t] += sh[t + o]; __syncthreads(); }
    if (t == 0) g_partial[b] = sh[0];
}
__global__ void __launch_bounds__(256) reduce_absw_2() {
    __shared__ float sh[256];
    int t = threadIdx.x;
    float s = g_partial[t] + g_partial[t + 256];
    if (t < 64) s += g_partial[t + 512];
    sh[t] = s;
    __syncthreads();
    for (int o = 128; o > 0; o >>= 1) { if (t < o) sh[t] += sh[t + o]; __syncthreads(); }
    if (t == 0) g_E = sh[0] / (float)NW_ELEM;
}

// ---------------- 2. quantize acts -> padded s8 packs --------------------------
__global__ void __launch_bounds__(256) quantize_x(const float* __restrict__ x) {
    int idx = blockIdx.x * 256 + threadIdx.x;          // NB*HP*WP*64
    if (idx >= NB * HP * WP * 64) return;
    int c4 = idx & 63;
    int t  = idx >> 6;
    int wp = t % WP; t /= WP;
    int hp = t % HP;
    int n  = t / HP;
    int pack = 0;
    if (hp >= 1 && hp <= HH && wp >= 1 && wp <= WW) {
        const float4 v = *reinterpret_cast<const float4*>(
            x + (((size_t)(n * HH + (hp - 1)) * WW + (wp - 1)) * CI + c4 * 4));
        int a0 = __float2int_rn(fminf(1.0f, fabsf(v.x)) * 7.0f);
        int a1 = __float2int_rn(fminf(1.0f, fabsf(v.y)) * 7.0f);
        int a2 = __float2int_rn(fminf(1.0f, fabsf(v.z)) * 7.0f);
        int a3 = __float2int_rn(fminf(1.0f, fabsf(v.w)) * 7.0f);
        pack = (a0 & 0xff) | ((a1 & 0xff) << 8) | ((a2 & 0xff) << 16) | ((a3 & 0xff) << 24);
    }
    g_act[idx] = pack;
}

// ---------------- 3. weight signs -> [co][k9][ci] s8 packs ---------------------
__global__ void __launch_bounds__(256) wtrans(const float* __restrict__ W) {
    int idx = blockIdx.x * 256 + threadIdx.x;          // 147456 = 576*256
    int co = idx & 255;
    int cp = (idx >> 8) & 63;
    int k9 = idx >> 14;
    int pack = 0;
#pragma unroll
    for (int j = 0; j < 4; j++) {
        float f = W[((size_t)(k9 * CI + cp * 4 + j)) * CO + co];
        int s = (f > 0.0f) - (f < 0.0f);
        pack |= (s & 0xff) << (8 * j);
    }
    g_wt[co * 576 + k9 * 64 + cp] = pack;
}

// ---------------- 4. implicit-GEMM conv via IMMA m16n8k32 ----------------------
// grid (784, 2); block 256 = 8 warps (4 M-groups x 2 N-groups), warp tile 32x64
__global__ void __launch_bounds__(256, 2) conv_mma(const float* __restrict__ bias,
                                                   float* __restrict__ out) {
    __shared__ char sbuf[STAGES * STAGE_BYTES];        // 36864 B
    __shared__ float sbias[128];

    const int tid = threadIdx.x;
    const int pbase = blockIdx.x * 128;
    const int nbase = blockIdx.y * 128;

    if (tid < 128) sbias[tid] = bias[nbase + tid];

    // producer: thread -> one A 16B chunk + one B 16B chunk per k-step
    const int pr = tid >> 1, half = tid & 1;
    {
        // nothing
    }
    const int P = pbase + pr;
    const int pn = P / 3136;
    const int prm = P - pn * 3136;
    const int ph = prm / 56;
    const int pw = prm - ph * 56;
    const char* aBase = (const char*)g_act
        + ((size_t)((pn * HP + ph) * WP + pw)) * 256 + half * 16;
    const char* bBase = (const char*)g_wt + (size_t)(nbase + pr) * 2304 + half * 16;
    const uint32_t dstOff = pr * ROWPAD + half * 16;
    const uint32_t sb = smem_u32(sbuf);

    // consumer fragment offsets
    const int lane = tid & 31, wid = tid >> 5;
    const int mgrp = wid & 3;          // M offset = mgrp*32
    const int ngrp = wid >> 2;         // N offset = ngrp*64
    const uint32_t aoff = (uint32_t)((mgrp * 32 + (lane >> 2)) * ROWPAD + (lane & 3) * 4);
    const uint32_t boff = (uint32_t)((ngrp * 64 + (lane >> 2)) * ROWPAD + (lane & 3) * 4) + A_BYTES;

    int acc[2][8][4];
#pragma unroll
    for (int ma = 0; ma < 2; ma++)
#pragma unroll
        for (int na = 0; na < 8; na++)
#pragma unroll
            for (int j = 0; j < 4; j++) acc[ma][na][j] = 0;

    // prologue: stages 0,1
#pragma unroll
    for (int ks = 0; ks < STAGES - 1; ks++) {
        const int k9 = ks >> 3, cc = ks & 7;
        const int kh = k9 / 3, kw = k9 - kh * 3;
        const uint32_t slot = sb + ks * STAGE_BYTES;
        CP_ASYNC16(slot + dstOff, aBase + (kh * WP + kw) * 256 + cc * 32);
        CP_ASYNC16(slot + A_BYTES + dstOff, bBase + k9 * 256 + cc * 32);
        CP_COMMIT();
    }

    int slotIdx = 0;                    // ks % 3
    int loadSlot = STAGES - 1;          // (ks+2) % 3
    for (int ks = 0; ks < NKS; ks++) {
        CP_WAIT(STAGES - 2);            // stage ks resident
        __syncthreads();                // visibility + WAR protection for loadSlot

        // issue stage ks+2
        {
            const int kn = ks + STAGES - 1;
            if (kn < NKS) {
                const int k9 = kn >> 3, cc = kn & 7;
                const int kh = k9 / 3, kw = k9 - kh * 3;
                const uint32_t slot = sb + loadSlot * STAGE_BYTES;
                CP_ASYNC16(slot + dstOff, aBase + (kh * WP + kw) * 256 + cc * 32);
                CP_ASYNC16(slot + A_BYTES + dstOff, bBase + k9 * 256 + cc * 32);
            }
            CP_COMMIT();
        }

        // consume stage ks
        const char* s = sbuf + slotIdx * STAGE_BYTES;
        uint32_t af[2][4];
#pragma unroll
        for (int ma = 0; ma < 2; ma++) {
            const char* ab = s + aoff + ma * (16 * ROWPAD);
            af[ma][0] = *(const uint32_t*)(ab);
            af[ma][1] = *(const uint32_t*)(ab + 8 * ROWPAD);
            af[ma][2] = *(const uint32_t*)(ab + 16);
            af[ma][3] = *(const uint32_t*)(ab + 8 * ROWPAD + 16);
        }
        uint32_t bf[8][2];
#pragma unroll
        for (int na = 0; na < 8; na++) {
            const char* bb = s + boff + na * (8 * ROWPAD);
            bf[na][0] = *(const uint32_t*)(bb);
            bf[na][1] = *(const uint32_t*)(bb + 16);
        }
#pragma unroll
        for (int na = 0; na < 8; na++)
#pragma unroll
            for (int ma = 0; ma < 2; ma++)
                imma16832(acc[ma][na], af[ma][0], af[ma][1], af[ma][2], af[ma][3],
                          bf[na][0], bf[na][1]);

        slotIdx++;  if (slotIdx == STAGES) slotIdx = 0;
        loadSlot++; if (loadSlot == STAGES) loadSlot = 0;
    }

    // epilogue: acc * (E/7) + bias
    const float scale = g_E * (1.0f / 7.0f);
    const int orow0 = pbase + mgrp * 32 + (lane >> 2);
    const int ocol0 = nbase + ngrp * 64 + (lane & 3) * 2;
#pragma unroll
    for (int ma = 0; ma < 2; ma++) {
#pragma unroll
        for (int na = 0; na < 8; na++) {
            const int row = orow0 + ma * 16;
            const int col = ocol0 + na * 8;
            const float b0 = sbias[col - nbase];
            const float b1 = sbias[col - nbase + 1];
            float2 v0, v1;
            v0.x = (float)acc[ma][na][0] * scale + b0;
            v0.y = (float)acc[ma][na][1] * scale + b1;
            v1.x = (float)acc[ma][na][2] * scale + b0;
            v1.y = (float)acc[ma][na][3] * scale + b1;
            *reinterpret_cast<float2*>(out + (size_t)row * CO + col) = v0;
            *reinterpret_cast<float2*>(out + (size_t)(row + 8) * CO + col) = v1;
        }
    }
}

// ---------------- launch -------------------------------------------------------
extern "C" void kernel_launch(void* const* d_in, const int* in_sizes, int n_in,
                              void* d_out, int out_size) {
    const float* x = (const float*)d_in[0];
    const float* W = (const float*)d_in[1];
    const float* b = (const float*)d_in[2];
    float* out = (float*)d_out;

    reduce_absw_1<<<576, 256>>>(W);
    reduce_absw_2<<<1, 256>>>();

    int qtot = NB * HP * WP * 64;
    quantize_x<<<(qtot + 255) / 256, 256>>>(x);

    wtrans<<<576, 256>>>(W);

    dim3 grid(NTILE, 2);
    conv_mma<<<grid, 256>>>(b, out);
}